// round 1
// baseline (speedup 1.0000x reference)
#include <cuda_runtime.h>
#include <cstdint>

#define B_TOTAL   8192
#define LEAK      0.01f
#define BN_EPS    1e-5f

// -------------------- global scratch (allocation-free rule) --------------------
// conv1 output, padded [64][12][11], batch-minor
__device__ float g_conv[64 * 12 * 11 * B_TOTAL];          // 276.8 MB
// y1: post-lrelu, pre-BN  [16][50][B]
__device__ float g_y1[16 * 50 * B_TOTAL];
// y2: post-lrelu, pre-BN  [8][66][B]
__device__ float g_y2[8 * 66 * B_TOTAL];
// y3: post-lrelu, pre-BN  [8][48][B]
__device__ float g_y3[8 * 48 * B_TOTAL];
// per-block BN stat partials
__device__ float g_part1[1600 * 32];
__device__ float g_part2[2112 * 16];
__device__ float g_part3[1536 * 16];
// per-channel BN affine: bn(x) = A*x + Bs
__device__ float g_bnA1[16], g_bnB1[16];
__device__ float g_bnA2[8],  g_bnB2[8];
__device__ float g_bnA3[8],  g_bnB3[8];

__device__ __forceinline__ float lrelu(float v) { return v < 0.f ? LEAK * v : v; }
__device__ __forceinline__ float wsum(float v) {
#pragma unroll
    for (int s = 16; s; s >>= 1) v += __shfl_xor_sync(0xffffffffu, v, s);
    return v;
}

// ============================ K0: conv1 + lrelu + pad =========================
// grid (32 batch-tiles, 8 channel-groups), block 256. Each thread = 1 sample.
#define SMEM0 ((256 * 91 + 32 + 8) * 4)
__global__ void k0_conv1(const float* __restrict__ img,
                         const float* __restrict__ w1,
                         const float* __restrict__ b1) {
    extern __shared__ float sm0[];
    float* simg = sm0;                 // [256][91] padded stride
    float* sw   = sm0 + 256 * 91;      // [8][4]
    float* sb   = sw + 32;             // [8]
    const int t  = threadIdx.x;
    const int B0 = blockIdx.x * 256;
    const int c0 = blockIdx.y * 8;

#pragma unroll 1
    for (int i = 0; i < 90; ++i) {
        int f = i * 256 + t;
        int s = f / 90, off = f - s * 90;
        simg[s * 91 + off] = img[(B0 + s) * 90 + off];
    }
    if (t < 32) sw[t] = w1[c0 * 4 + t];
    if (t < 8)  sb[t] = b1[c0 + t];
    __syncthreads();

    const float* my = simg + t * 91;
#pragma unroll 1
    for (int cc = 0; cc < 8; ++cc) {
        const int c = c0 + cc;
        const float w00 = sw[cc * 4 + 0], w01 = sw[cc * 4 + 1];
        const float w10 = sw[cc * 4 + 2], w11 = sw[cc * 4 + 3];
        const float bb = sb[cc];
        float* outc = g_conv + (size_t)c * 132 * B_TOTAL + B0 + t;
#pragma unroll 1
        for (int r = 0; r < 12; ++r) {
#pragma unroll
            for (int col = 0; col < 11; ++col) {
                float v = 0.f;
                if (r >= 1 && r <= 10 && col >= 1 && col <= 9) {
                    int h = r - 1, w = col - 1;
                    float x00 = my[h * 9 + w];
                    float x01 = (w + 1 <= 8) ? my[h * 9 + w + 1] : 0.f;
                    float x10 = (h + 1 <= 9) ? my[(h + 1) * 9 + w] : 0.f;
                    float x11 = (h + 1 <= 9 && w + 1 <= 8) ? my[(h + 1) * 9 + w + 1] : 0.f;
                    v = fmaf(x00, w00, fmaf(x01, w01, fmaf(x10, w10, fmaf(x11, w11, bb))));
                    v = lrelu(v);
                }
                outc[(r * 11 + col) * B_TOTAL] = v;
            }
        }
    }
}

// ============================ K1: LC1 GEMM ====================================
// grid (50 locations, 32 batch-tiles), block 256.
// C[256 samples x 16 ch], K = 576 (c*9 + i*3 + j), kc = 64 chunks.
// smem: As[64][256] (64KB) | Ws[576][16] (36.9KB) | red[32]
#define SMEM1 ((16384 + 9216 + 32) * 4)
__global__ void k1_lc1(const float* __restrict__ lcw, const float* __restrict__ lcb) {
    extern __shared__ float sm1[];
    float* As  = sm1;                  // 16384 floats
    float* Ws  = sm1 + 16384;          // 9216 floats
    float* red = Ws + 9216;            // 32 floats
    const int t   = threadIdx.x;
    const int loc = blockIdx.x;        // 0..49
    const int B0  = blockIdx.y * 256;
    const int h   = loc / 5, w = loc - h * 5;

    // W fill: 1024 (o,c) runs of 9
#pragma unroll
    for (int rr = 0; rr < 4; ++rr) {
        int rid = rr * 256 + t;
        int o = rid >> 6, c = rid & 63;
        const float* src = lcw + ((size_t)(o * 64 + c) * 50 + loc) * 9;
        int kb = c * 9;
#pragma unroll
        for (int m = 0; m < 9; ++m) Ws[(kb + m) * 16 + o] = src[m];
    }
    if (t < 32) red[t] = 0.f;

    const int sg = t & 63, og = t >> 6;
    float acc[4][4];
#pragma unroll
    for (int a = 0; a < 4; ++a)
#pragma unroll
        for (int b = 0; b < 4; ++b) acc[a][b] = 0.f;

    const float4* A4 = ((const float4*)As) + sg;

#pragma unroll 1
    for (int k0 = 0; k0 < 576; k0 += 64) {
        __syncthreads();
        // A chunk fill: 4096 float4, 16 per thread
#pragma unroll
        for (int i = 0; i < 16; ++i) {
            int f = i * 256 + t;
            int kk = f >> 6, sq = f & 63;
            int k = k0 + kk;
            int c = k / 9, m = k - c * 9;
            int i3 = m / 3, j3 = m - i3 * 3;
            const float4* gp = (const float4*)(g_conv +
                ((size_t)((c * 12 + h + i3) * 11 + 2 * w + j3)) * B_TOTAL + B0) + sq;
            ((float4*)As)[f] = *gp;
        }
        __syncthreads();
        const float4* Wk = ((const float4*)Ws) + og + (size_t)k0 * 4;
#pragma unroll 16
        for (int kk = 0; kk < 64; ++kk) {
            float4 a = A4[kk * 64];
            float4 wv = Wk[kk * 4];
            acc[0][0] += a.x * wv.x; acc[0][1] += a.x * wv.y; acc[0][2] += a.x * wv.z; acc[0][3] += a.x * wv.w;
            acc[1][0] += a.y * wv.x; acc[1][1] += a.y * wv.y; acc[1][2] += a.y * wv.z; acc[1][3] += a.y * wv.w;
            acc[2][0] += a.z * wv.x; acc[2][1] += a.z * wv.y; acc[2][2] += a.z * wv.z; acc[2][3] += a.z * wv.w;
            acc[3][0] += a.w * wv.x; acc[3][1] += a.w * wv.y; acc[3][2] += a.w * wv.z; acc[3][3] += a.w * wv.w;
        }
    }

    // epilogue: bias + lrelu + store + stats
    const int o0 = og * 4;
#pragma unroll
    for (int oi = 0; oi < 4; ++oi) {
        const float bv = lcb[(o0 + oi) * 50 + loc];
        float v0 = lrelu(acc[0][oi] + bv);
        float v1 = lrelu(acc[1][oi] + bv);
        float v2 = lrelu(acc[2][oi] + bv);
        float v3 = lrelu(acc[3][oi] + bv);
        float4 o4 = make_float4(v0, v1, v2, v3);
        ((float4*)(g_y1 + ((size_t)(o0 + oi) * 50 + loc) * B_TOTAL + B0))[sg] = o4;
        float s = wsum(v0 + v1 + v2 + v3);
        float q = wsum(v0 * v0 + v1 * v1 + v2 * v2 + v3 * v3);
        if ((t & 31) == 0) {
            atomicAdd(&red[(o0 + oi) * 2 + 0], s);
            atomicAdd(&red[(o0 + oi) * 2 + 1], q);
        }
    }
    __syncthreads();
    if (t < 32) g_part1[(blockIdx.y * 50 + loc) * 32 + t] = red[t];
}

// ============================ K3: BN1 + pad + LC2 =============================
// grid (66 locations, 32 batch-tiles), block 256. C[256 x 8], K = 64.
#define SMEM3 ((16384 + 512 + 16 + 16 + 16) * 4)
__global__ void k3_lc2(const float* __restrict__ lcw, const float* __restrict__ lcb) {
    extern __shared__ float sm3[];
    float* As  = sm3;            // 16384
    float* Ws  = sm3 + 16384;    // 512
    float* bnA = Ws + 512;       // 16
    float* bnB = bnA + 16;       // 16
    float* red = bnB + 16;       // 16
    const int t   = threadIdx.x;
    const int loc = blockIdx.x;  // 0..65
    const int B0  = blockIdx.y * 256;
    const int h2  = loc / 6, w2 = loc - h2 * 6;

    if (t < 16) { bnA[t] = g_bnA1[t]; bnB[t] = g_bnB1[t]; red[t] = 0.f; }
#pragma unroll
    for (int rr = 0; rr < 2; ++rr) {
        int idx = rr * 256 + t;  // k*8 + o
        int o = idx & 7, k = idx >> 3;
        int c = k >> 2, m = k & 3;
        Ws[idx] = lcw[(size_t)(((o * 16 + c) * 11 + h2) * 6 + w2) * 4 + m];
    }
    __syncthreads();

#pragma unroll
    for (int i = 0; i < 16; ++i) {
        int f = i * 256 + t;
        int kk = f >> 6, sq = f & 63;
        int c = kk >> 2, m = kk & 3;
        int hp = h2 + (m >> 1), wp = w2 + (m & 1);
        float4 v = make_float4(0.f, 0.f, 0.f, 0.f);
        if (hp >= 1 && hp <= 10 && wp >= 1 && wp <= 5) {
            float4 y = ((const float4*)(g_y1 +
                ((size_t)c * 50 + (hp - 1) * 5 + (wp - 1)) * B_TOTAL + B0))[sq];
            float a = bnA[c], b = bnB[c];
            v = make_float4(fmaf(a, y.x, b), fmaf(a, y.y, b), fmaf(a, y.z, b), fmaf(a, y.w, b));
        }
        ((float4*)As)[f] = v;
    }
    __syncthreads();

    const int sg = t & 63, og = t >> 6;
    const int o0 = og * 2;
    float acc[4][2];
#pragma unroll
    for (int a = 0; a < 4; ++a) { acc[a][0] = 0.f; acc[a][1] = 0.f; }
    const float4* A4 = ((const float4*)As) + sg;
    const float2* W2 = ((const float2*)Ws) + og;
#pragma unroll
    for (int kk = 0; kk < 64; ++kk) {
        float4 a = A4[kk * 64];
        float2 wv = W2[kk * 4];
        acc[0][0] += a.x * wv.x; acc[0][1] += a.x * wv.y;
        acc[1][0] += a.y * wv.x; acc[1][1] += a.y * wv.y;
        acc[2][0] += a.z * wv.x; acc[2][1] += a.z * wv.y;
        acc[3][0] += a.w * wv.x; acc[3][1] += a.w * wv.y;
    }
#pragma unroll
    for (int oi = 0; oi < 2; ++oi) {
        const float bv = lcb[(o0 + oi) * 66 + loc];
        float v0 = lrelu(acc[0][oi] + bv);
        float v1 = lrelu(acc[1][oi] + bv);
        float v2 = lrelu(acc[2][oi] + bv);
        float v3 = lrelu(acc[3][oi] + bv);
        ((float4*)(g_y2 + ((size_t)(o0 + oi) * 66 + loc) * B_TOTAL + B0))[sg] =
            make_float4(v0, v1, v2, v3);
        float s = wsum(v0 + v1 + v2 + v3);
        float q = wsum(v0 * v0 + v1 * v1 + v2 * v2 + v3 * v3);
        if ((t & 31) == 0) {
            atomicAdd(&red[(o0 + oi) * 2 + 0], s);
            atomicAdd(&red[(o0 + oi) * 2 + 1], q);
        }
    }
    __syncthreads();
    if (t < 16) g_part2[(blockIdx.y * 66 + loc) * 16 + t] = red[t];
}

// ============================ K5: BN2 + pad + LC3 =============================
// grid (48 locations, 32 batch-tiles), block 256. C[256 x 8], K = 32.
__global__ void k5_lc3(const float* __restrict__ lcw, const float* __restrict__ lcb) {
    __shared__ __align__(16) float As[8192];   // 256 x 32
    __shared__ float Ws[256];                  // 32 x 8
    __shared__ float bnA[8], bnB[8], red[16];
    const int t   = threadIdx.x;
    const int loc = blockIdx.x;  // 0..47
    const int B0  = blockIdx.y * 256;
    const int h3  = loc >> 2, w3 = loc & 3;

    if (t < 8)  { bnA[t] = g_bnA2[t]; bnB[t] = g_bnB2[t]; }
    if (t < 16) red[t] = 0.f;
    if (t < 256) {
        int o = t & 7, k = t >> 3;
        int c = k >> 2, m = k & 3;
        Ws[t] = lcw[(size_t)(((o * 8 + c) * 12 + h3) * 4 + w3) * 4 + m];
    }
    __syncthreads();

#pragma unroll
    for (int i = 0; i < 8; ++i) {
        int f = i * 256 + t;
        int kk = f >> 6, sq = f & 63;
        int c = kk >> 2, m = kk & 3;
        int hp = h3 + (m >> 1), wp = 2 * w3 + (m & 1);
        float4 v = make_float4(0.f, 0.f, 0.f, 0.f);
        if (hp >= 1 && hp <= 11 && wp >= 1 && wp <= 6) {
            float4 y = ((const float4*)(g_y2 +
                ((size_t)c * 66 + (hp - 1) * 6 + (wp - 1)) * B_TOTAL + B0))[sq];
            float a = bnA[c], b = bnB[c];
            v = make_float4(fmaf(a, y.x, b), fmaf(a, y.y, b), fmaf(a, y.z, b), fmaf(a, y.w, b));
        }
        ((float4*)As)[f] = v;
    }
    __syncthreads();

    const int sg = t & 63, og = t >> 6;
    const int o0 = og * 2;
    float acc[4][2];
#pragma unroll
    for (int a = 0; a < 4; ++a) { acc[a][0] = 0.f; acc[a][1] = 0.f; }
    const float4* A4 = ((const float4*)As) + sg;
    const float2* W2 = ((const float2*)Ws) + og;
#pragma unroll
    for (int kk = 0; kk < 32; ++kk) {
        float4 a = A4[kk * 64];
        float2 wv = W2[kk * 4];
        acc[0][0] += a.x * wv.x; acc[0][1] += a.x * wv.y;
        acc[1][0] += a.y * wv.x; acc[1][1] += a.y * wv.y;
        acc[2][0] += a.z * wv.x; acc[2][1] += a.z * wv.y;
        acc[3][0] += a.w * wv.x; acc[3][1] += a.w * wv.y;
    }
#pragma unroll
    for (int oi = 0; oi < 2; ++oi) {
        const float bv = lcb[(o0 + oi) * 48 + loc];
        float v0 = lrelu(acc[0][oi] + bv);
        float v1 = lrelu(acc[1][oi] + bv);
        float v2 = lrelu(acc[2][oi] + bv);
        float v3 = lrelu(acc[3][oi] + bv);
        ((float4*)(g_y3 + ((size_t)(o0 + oi) * 48 + loc) * B_TOTAL + B0))[sg] =
            make_float4(v0, v1, v2, v3);
        float s = wsum(v0 + v1 + v2 + v3);
        float q = wsum(v0 * v0 + v1 * v1 + v2 * v2 + v3 * v3);
        if ((t & 31) == 0) {
            atomicAdd(&red[(o0 + oi) * 2 + 0], s);
            atomicAdd(&red[(o0 + oi) * 2 + 1], q);
        }
    }
    __syncthreads();
    if (t < 16) g_part3[(blockIdx.y * 48 + loc) * 16 + t] = red[t];
}

// ============================ stat reducer ====================================
// 1 block, 1024 threads. stage: 0 -> BN1, 1 -> BN2, 2 -> BN3
__global__ void kred(int stage, int nb, int nch, float invN,
                     const float* __restrict__ gamma, const float* __restrict__ beta) {
    __shared__ float sm[1024];
    const float* part = (stage == 0) ? g_part1 : (stage == 1) ? g_part2 : g_part3;
    float* bnA = (stage == 0) ? g_bnA1 : (stage == 1) ? g_bnA2 : g_bnA3;
    float* bnB = (stage == 0) ? g_bnB1 : (stage == 1) ? g_bnB2 : g_bnB3;
    const int t = threadIdx.x;
    const int slots = 2 * nch;
    const int grp = t % slots;
    const int lane = t / slots;
    const int per = blockDim.x / slots;
    float s = 0.f;
    for (int i = lane; i < nb; i += per) s += part[i * slots + grp];
    sm[t] = s;
    __syncthreads();
    for (int step = per >> 1; step > 0; step >>= 1) {
        if (lane < step) sm[t] += sm[t + step * slots];
        __syncthreads();
    }
    if (t < nch) {
        float sum = sm[t * 2 + 0], sq = sm[t * 2 + 1];
        float mean = sum * invN;
        float var = sq * invN - mean * mean;
        float rs = rsqrtf(var + BN_EPS);
        float g = gamma[t];
        bnA[t] = g * rs;
        bnB[t] = beta[t] - mean * g * rs;
    }
}

// ============================ K7: BN3 + transpose to output ===================
// grid (12 feature-tiles of 32, 128 batch-tiles of 64), block 256
__global__ void k7_out(float* __restrict__ out) {
    __shared__ float tile[32][65];
    __shared__ float a3[8], b3[8];
    const int t  = threadIdx.x;
    const int f0 = blockIdx.x * 32;
    const int b0 = blockIdx.y * 64;
    if (t < 8) { a3[t] = g_bnA3[t]; b3[t] = g_bnB3[t]; }
    __syncthreads();
#pragma unroll
    for (int r = 0; r < 8; ++r) {
        int f = r * 4 + (t >> 6);
        int b = t & 63;
        float v = g_y3[(size_t)(f0 + f) * B_TOTAL + b0 + b];
        int c = (f0 + f) / 48;
        tile[f][b] = fmaf(a3[c], v, b3[c]);
    }
    __syncthreads();
#pragma unroll
    for (int r = 0; r < 8; ++r) {
        int f = t & 31;
        int b = r * 8 + (t >> 5);
        out[(size_t)(b0 + b) * 384 + f0 + f] = tile[f][b];
    }
}

// ============================ launch ==========================================
extern "C" void kernel_launch(void* const* d_in, const int* in_sizes, int n_in,
                              void* d_out, int out_size) {
    const float* image = (const float*)d_in[0];
    const float* c1w   = (const float*)d_in[1];
    const float* c1b   = (const float*)d_in[2];
    const float* lc1w  = (const float*)d_in[3];
    const float* lc1b  = (const float*)d_in[4];
    const float* lc2w  = (const float*)d_in[5];
    const float* lc2b  = (const float*)d_in[6];
    const float* lc3w  = (const float*)d_in[7];
    const float* lc3b  = (const float*)d_in[8];
    const float* g1    = (const float*)d_in[9];
    const float* be1   = (const float*)d_in[10];
    const float* g2    = (const float*)d_in[11];
    const float* be2   = (const float*)d_in[12];
    const float* g3    = (const float*)d_in[13];
    const float* be3   = (const float*)d_in[14];
    float* out = (float*)d_out;

    cudaFuncSetAttribute(k0_conv1, cudaFuncAttributeMaxDynamicSharedMemorySize, SMEM0);
    cudaFuncSetAttribute(k1_lc1,   cudaFuncAttributeMaxDynamicSharedMemorySize, SMEM1);
    cudaFuncSetAttribute(k3_lc2,   cudaFuncAttributeMaxDynamicSharedMemorySize, SMEM3);

    k0_conv1<<<dim3(32, 8),   256, SMEM0>>>(image, c1w, c1b);
    k1_lc1  <<<dim3(50, 32),  256, SMEM1>>>(lc1w, lc1b);
    kred    <<<1, 1024>>>(0, 1600, 16, 1.0f / (8192.0f * 50.0f),  g1, be1);
    k3_lc2  <<<dim3(66, 32),  256, SMEM3>>>(lc2w, lc2b);
    kred    <<<1, 1024>>>(1, 2112, 8,  1.0f / (8192.0f * 66.0f),  g2, be2);
    k5_lc3  <<<dim3(48, 32),  256>>>(lc3w, lc3b);
    kred    <<<1, 1024>>>(2, 1536, 8,  1.0f / (8192.0f * 48.0f),  g3, be3);
    k7_out  <<<dim3(12, 128), 256>>>(out);
}

// round 2
// speedup vs baseline: 1.0127x; 1.0127x over previous
#include <cuda_runtime.h>
#include <cstdint>

#define B_TOTAL   8192
#define LEAK      0.01f
#define BN_EPS    1e-5f

// -------------------- global scratch (allocation-free rule) --------------------
// conv1 output, UNPADDED [64][10][9], batch-minor (padding handled by predicates)
__device__ float g_conv[64 * 90 * B_TOTAL];               // 188.7 MB
__device__ float g_y1[16 * 50 * B_TOTAL];
__device__ float g_y2[8 * 66 * B_TOTAL];
__device__ float g_y3[8 * 48 * B_TOTAL];
__device__ float g_part1[800 * 32];
__device__ float g_part2[1056 * 16];
__device__ float g_part3[768 * 16];
__device__ float g_bnA1[16], g_bnB1[16];
__device__ float g_bnA2[8],  g_bnB2[8];
__device__ float g_bnA3[8],  g_bnB3[8];

__device__ __forceinline__ float lrelu(float v) { return v < 0.f ? LEAK * v : v; }
__device__ __forceinline__ float wsum(float v) {
#pragma unroll
    for (int s = 16; s; s >>= 1) v += __shfl_xor_sync(0xffffffffu, v, s);
    return v;
}
__device__ __forceinline__ unsigned long long dup2(float v) {
    unsigned int u = __float_as_uint(v);
    return ((unsigned long long)u << 32) | (unsigned long long)u;
}
#define FMA2(d, a, b) asm("fma.rn.f32x2 %0, %1, %2, %0;" : "+l"(d) : "l"(a), "l"(b))
#define UNPK(lo, hi, v) asm("mov.b64 {%0, %1}, %2;" : "=f"(lo), "=f"(hi) : "l"(v))

// ============================ K0: conv1 + lrelu ===============================
// grid (32 batch-tiles of 256, 8 channel-groups), block 256.
// thread = (sample-quad q, 2-channel group cg). float4 stores.
#define SMEM0 ((256 * 91 + 32 + 8) * 4)
__global__ void k0_conv1(const float* __restrict__ img,
                         const float* __restrict__ w1,
                         const float* __restrict__ b1) {
    extern __shared__ float sm0[];
    float* simg = sm0;                 // [256][91]
    float* sw   = sm0 + 256 * 91;      // [8][4]
    float* sb   = sw + 32;             // [8]
    const int t  = threadIdx.x;
    const int B0 = blockIdx.x * 256;
    const int c0 = blockIdx.y * 8;

#pragma unroll 1
    for (int i = 0; i < 90; ++i) {
        int f = i * 256 + t;
        int s = f / 90, off = f - s * 90;
        simg[s * 91 + off] = img[(B0 + s) * 90 + off];
    }
    if (t < 32) sw[t] = w1[c0 * 4 + t];
    if (t < 8)  sb[t] = b1[c0 + t];
    __syncthreads();

    const int q  = t & 63;
    const int cg = t >> 6;
    float W00[2], W01[2], W10[2], W11[2], BB[2];
#pragma unroll
    for (int c2 = 0; c2 < 2; ++c2) {
        int cc = cg * 2 + c2;
        W00[c2] = sw[cc * 4 + 0]; W01[c2] = sw[cc * 4 + 1];
        W10[c2] = sw[cc * 4 + 2]; W11[c2] = sw[cc * 4 + 3];
        BB[c2]  = sb[cc];
    }

#pragma unroll 1
    for (int h = 0; h < 10; ++h) {
        float a[4][9], b[4][9];
        const bool hb = (h < 9);
#pragma unroll
        for (int s = 0; s < 4; ++s) {
            const float* rp = simg + (q * 4 + s) * 91 + h * 9;
#pragma unroll
            for (int w = 0; w < 9; ++w) {
                a[s][w] = rp[w];
                b[s][w] = hb ? rp[9 + w] : 0.f;
            }
        }
#pragma unroll
        for (int c2 = 0; c2 < 2; ++c2) {
            const int c = c0 + cg * 2 + c2;
            float* op = g_conv + ((size_t)c * 90 + h * 9) * B_TOTAL + B0 + q * 4;
            const float w00 = W00[c2], w01 = W01[c2], w10 = W10[c2], w11 = W11[c2], bv = BB[c2];
#pragma unroll
            for (int w = 0; w < 9; ++w) {
                float v[4];
#pragma unroll
                for (int s = 0; s < 4; ++s) {
                    float t0 = fmaf(a[s][w], w00, bv);
                    if (w < 8) t0 = fmaf(a[s][w + 1], w01, t0);
                    t0 = fmaf(b[s][w], w10, t0);
                    if (w < 8) t0 = fmaf(b[s][w + 1], w11, t0);
                    v[s] = lrelu(t0);
                }
                ((float4*)(op + (size_t)w * B_TOTAL))[0] = make_float4(v[0], v[1], v[2], v[3]);
            }
        }
    }
}

// ============================ K1: LC1 GEMM (f32x2) ============================
// grid (50 locations, 16 batch-tiles of 512), block 256.
// C[512 samples x 16 ch], K = 576 in 18 chunks of 32. thread: 4 samples x 8 ch.
#define KC1   32
#define NCHK1 18
#define SMEM1 (65536 + 73728 + 128)
__global__ void k1_lc1(const float* __restrict__ lcw, const float* __restrict__ lcb) {
    extern __shared__ float sm1[];
    float* As = sm1;                                          // 32 x 512 floats
    unsigned long long* Wd = (unsigned long long*)(sm1 + 16384); // [576][16] dup pairs
    float* red = (float*)(Wd + 9216);                          // 32 floats
    const int t   = threadIdx.x;
    const int loc = blockIdx.x;
    const int B0  = blockIdx.y * 512;
    const int h   = loc / 5, w = loc - h * 5;

    // weight fill: 1024 (o,c) runs of 9, duplicated into f32x2 pairs
#pragma unroll
    for (int rr = 0; rr < 4; ++rr) {
        int rid = rr * 256 + t;
        int o = rid >> 6, c = rid & 63;
        const float* src = lcw + ((size_t)(o * 64 + c) * 50 + loc) * 9;
        int kb = c * 9;
#pragma unroll
        for (int m = 0; m < 9; ++m) Wd[(kb + m) * 16 + o] = dup2(src[m]);
    }
    if (t < 32) red[t] = 0.f;

    const int sg = t & 127;          // sample quad 0..127
    const int og = t >> 7;           // 0/1 -> channels og*8..og*8+7
    unsigned long long acc[2][8] = {};

    float4 pf[16];
    // prefetch chunk 0
    {
        const int k0 = 0;
#pragma unroll
        for (int i = 0; i < 16; ++i) {
            int f = i * 256 + t;
            int kk = f >> 7, sq = f & 127;
            int k = k0 + kk;
            int c = k / 9, m = k - c * 9;
            int i3 = m / 3, j3 = m - i3 * 3;
            int r = h + i3, cc = 2 * w + j3;
            float4 v = make_float4(0.f, 0.f, 0.f, 0.f);
            if (r >= 1 && r <= 10 && cc >= 1 && cc <= 9)
                v = ((const float4*)(g_conv +
                    ((size_t)((c * 10 + r - 1) * 9 + cc - 1)) * B_TOTAL + B0))[sq];
            pf[i] = v;
        }
    }

    const ulonglong2* A2base = ((const ulonglong2*)As) + sg;
    const ulonglong2* W2 = (const ulonglong2*)Wd;

#pragma unroll 1
    for (int ch = 0; ch < NCHK1; ++ch) {
        __syncthreads();
#pragma unroll
        for (int i = 0; i < 16; ++i) ((float4*)As)[i * 256 + t] = pf[i];
        __syncthreads();
        if (ch + 1 < NCHK1) {
            const int k0 = (ch + 1) * KC1;
#pragma unroll
            for (int i = 0; i < 16; ++i) {
                int f = i * 256 + t;
                int kk = f >> 7, sq = f & 127;
                int k = k0 + kk;
                int c = k / 9, m = k - c * 9;
                int i3 = m / 3, j3 = m - i3 * 3;
                int r = h + i3, cc = 2 * w + j3;
                float4 v = make_float4(0.f, 0.f, 0.f, 0.f);
                if (r >= 1 && r <= 10 && cc >= 1 && cc <= 9)
                    v = ((const float4*)(g_conv +
                        ((size_t)((c * 10 + r - 1) * 9 + cc - 1)) * B_TOTAL + B0))[sq];
                pf[i] = v;
            }
        }
        const int kw = ch * KC1;
#pragma unroll 8
        for (int kk = 0; kk < KC1; ++kk) {
            ulonglong2 av = A2base[kk * 128];
            const ulonglong2* wp = W2 + (size_t)(kw + kk) * 8 + og * 4;
            ulonglong2 w0 = wp[0], w1 = wp[1], w2 = wp[2], w3 = wp[3];
            FMA2(acc[0][0], av.x, w0.x); FMA2(acc[0][1], av.x, w0.y);
            FMA2(acc[0][2], av.x, w1.x); FMA2(acc[0][3], av.x, w1.y);
            FMA2(acc[0][4], av.x, w2.x); FMA2(acc[0][5], av.x, w2.y);
            FMA2(acc[0][6], av.x, w3.x); FMA2(acc[0][7], av.x, w3.y);
            FMA2(acc[1][0], av.y, w0.x); FMA2(acc[1][1], av.y, w0.y);
            FMA2(acc[1][2], av.y, w1.x); FMA2(acc[1][3], av.y, w1.y);
            FMA2(acc[1][4], av.y, w2.x); FMA2(acc[1][5], av.y, w2.y);
            FMA2(acc[1][6], av.y, w3.x); FMA2(acc[1][7], av.y, w3.y);
        }
    }

    // epilogue: bias + lrelu + store + stats
#pragma unroll
    for (int oi = 0; oi < 8; ++oi) {
        const int o = og * 8 + oi;
        const float bv = lcb[o * 50 + loc];
        float p0l, p0h, p1l, p1h;
        UNPK(p0l, p0h, acc[0][oi]);
        UNPK(p1l, p1h, acc[1][oi]);
        float v0 = lrelu(p0l + bv), v1 = lrelu(p0h + bv);
        float v2 = lrelu(p1l + bv), v3 = lrelu(p1h + bv);
        ((float4*)(g_y1 + ((size_t)o * 50 + loc) * B_TOTAL + B0))[sg] =
            make_float4(v0, v1, v2, v3);
        float s = wsum(v0 + v1 + v2 + v3);
        float qq = wsum(v0 * v0 + v1 * v1 + v2 * v2 + v3 * v3);
        if ((t & 31) == 0) {
            atomicAdd(&red[o * 2 + 0], s);
            atomicAdd(&red[o * 2 + 1], qq);
        }
    }
    __syncthreads();
    if (t < 32) g_part1[(blockIdx.y * 50 + loc) * 32 + t] = red[t];
}

// ============================ K3: BN1 + pad + LC2 (f32x2) =====================
// grid (66 locations, 16 batch-tiles of 512), block 256. K = 64, single chunk.
#define SMEM3 (131072 + 4096 + 4 * 48)
__global__ void k3_lc2(const float* __restrict__ lcw, const float* __restrict__ lcb) {
    extern __shared__ float sm3[];
    float* As = sm3;                                           // 64 x 512 floats
    unsigned long long* Wd = (unsigned long long*)(sm3 + 32768); // [64][8]
    float* bnA = (float*)(Wd + 512);
    float* bnB = bnA + 16;
    float* red = bnB + 16;
    const int t   = threadIdx.x;
    const int loc = blockIdx.x;
    const int B0  = blockIdx.y * 512;
    const int h2  = loc / 6, w2 = loc - h2 * 6;

    if (t < 16) { bnA[t] = g_bnA1[t]; bnB[t] = g_bnB1[t]; red[t] = 0.f; }
#pragma unroll
    for (int rr = 0; rr < 2; ++rr) {
        int idx = rr * 256 + t;          // k*8 + o
        int o = idx & 7, k = idx >> 3;
        int c = k >> 2, m = k & 3;
        Wd[idx] = dup2(lcw[(size_t)(((o * 16 + c) * 11 + h2) * 6 + w2) * 4 + m]);
    }
    __syncthreads();

#pragma unroll
    for (int i = 0; i < 32; ++i) {
        int f = i * 256 + t;
        int kk = f >> 7, sq = f & 127;
        int c = kk >> 2, m = kk & 3;
        int hp = h2 + (m >> 1), wp = w2 + (m & 1);
        float4 v = make_float4(0.f, 0.f, 0.f, 0.f);
        if (hp >= 1 && hp <= 10 && wp >= 1 && wp <= 5) {
            float4 y = ((const float4*)(g_y1 +
                ((size_t)c * 50 + (hp - 1) * 5 + (wp - 1)) * B_TOTAL + B0))[sq];
            float a = bnA[c], b = bnB[c];
            v = make_float4(fmaf(a, y.x, b), fmaf(a, y.y, b), fmaf(a, y.z, b), fmaf(a, y.w, b));
        }
        ((float4*)As)[f] = v;
    }
    __syncthreads();

    const int sg = t & 127;
    const int og = t >> 7;               // channels og*4..og*4+3
    unsigned long long acc[2][4] = {};
    const ulonglong2* A2 = ((const ulonglong2*)As) + sg;
    const ulonglong2* W2 = (const ulonglong2*)Wd;
#pragma unroll 8
    for (int kk = 0; kk < 64; ++kk) {
        ulonglong2 av = A2[kk * 128];
        const ulonglong2* wp = W2 + kk * 4 + og * 2;
        ulonglong2 w0 = wp[0], w1 = wp[1];
        FMA2(acc[0][0], av.x, w0.x); FMA2(acc[0][1], av.x, w0.y);
        FMA2(acc[0][2], av.x, w1.x); FMA2(acc[0][3], av.x, w1.y);
        FMA2(acc[1][0], av.y, w0.x); FMA2(acc[1][1], av.y, w0.y);
        FMA2(acc[1][2], av.y, w1.x); FMA2(acc[1][3], av.y, w1.y);
    }
#pragma unroll
    for (int oi = 0; oi < 4; ++oi) {
        const int o = og * 4 + oi;
        const float bv = lcb[o * 66 + loc];
        float p0l, p0h, p1l, p1h;
        UNPK(p0l, p0h, acc[0][oi]);
        UNPK(p1l, p1h, acc[1][oi]);
        float v0 = lrelu(p0l + bv), v1 = lrelu(p0h + bv);
        float v2 = lrelu(p1l + bv), v3 = lrelu(p1h + bv);
        ((float4*)(g_y2 + ((size_t)o * 66 + loc) * B_TOTAL + B0))[sg] =
            make_float4(v0, v1, v2, v3);
        float s = wsum(v0 + v1 + v2 + v3);
        float qq = wsum(v0 * v0 + v1 * v1 + v2 * v2 + v3 * v3);
        if ((t & 31) == 0) {
            atomicAdd(&red[o * 2 + 0], s);
            atomicAdd(&red[o * 2 + 1], qq);
        }
    }
    __syncthreads();
    if (t < 16) g_part2[(blockIdx.y * 66 + loc) * 16 + t] = red[t];
}

// ============================ K5: BN2 + pad + LC3 (f32x2) =====================
// grid (48 locations, 16 batch-tiles of 512), block 256. K = 32.
#define SMEM5 (65536 + 2048 + 4 * 32)
__global__ void k5_lc3(const float* __restrict__ lcw, const float* __restrict__ lcb) {
    extern __shared__ float sm5[];
    float* As = sm5;                                           // 32 x 512 floats
    unsigned long long* Wd = (unsigned long long*)(sm5 + 16384); // [32][8]
    float* bnA = (float*)(Wd + 256);
    float* bnB = bnA + 8;
    float* red = bnB + 8;
    const int t   = threadIdx.x;
    const int loc = blockIdx.x;
    const int B0  = blockIdx.y * 512;
    const int h3  = loc >> 2, w3 = loc & 3;

    if (t < 8)  { bnA[t] = g_bnA2[t]; bnB[t] = g_bnB2[t]; }
    if (t < 16) red[t] = 0.f;
    {
        int o = t & 7, k = t >> 3;
        int c = k >> 2, m = k & 3;
        Wd[t] = dup2(lcw[(size_t)(((o * 8 + c) * 12 + h3) * 4 + w3) * 4 + m]);
    }
    __syncthreads();

#pragma unroll
    for (int i = 0; i < 16; ++i) {
        int f = i * 256 + t;
        int kk = f >> 7, sq = f & 127;
        int c = kk >> 2, m = kk & 3;
        int hp = h3 + (m >> 1), wp = 2 * w3 + (m & 1);
        float4 v = make_float4(0.f, 0.f, 0.f, 0.f);
        if (hp >= 1 && hp <= 11 && wp >= 1 && wp <= 6) {
            float4 y = ((const float4*)(g_y2 +
                ((size_t)c * 66 + (hp - 1) * 6 + (wp - 1)) * B_TOTAL + B0))[sq];
            float a = bnA[c], b = bnB[c];
            v = make_float4(fmaf(a, y.x, b), fmaf(a, y.y, b), fmaf(a, y.z, b), fmaf(a, y.w, b));
        }
        ((float4*)As)[f] = v;
    }
    __syncthreads();

    const int sg = t & 127;
    const int og = t >> 7;
    unsigned long long acc[2][4] = {};
    const ulonglong2* A2 = ((const ulonglong2*)As) + sg;
    const ulonglong2* W2 = (const ulonglong2*)Wd;
#pragma unroll
    for (int kk = 0; kk < 32; ++kk) {
        ulonglong2 av = A2[kk * 128];
        const ulonglong2* wp = W2 + kk * 4 + og * 2;
        ulonglong2 w0 = wp[0], w1 = wp[1];
        FMA2(acc[0][0], av.x, w0.x); FMA2(acc[0][1], av.x, w0.y);
        FMA2(acc[0][2], av.x, w1.x); FMA2(acc[0][3], av.x, w1.y);
        FMA2(acc[1][0], av.y, w0.x); FMA2(acc[1][1], av.y, w0.y);
        FMA2(acc[1][2], av.y, w1.x); FMA2(acc[1][3], av.y, w1.y);
    }
#pragma unroll
    for (int oi = 0; oi < 4; ++oi) {
        const int o = og * 4 + oi;
        const float bv = lcb[o * 48 + loc];
        float p0l, p0h, p1l, p1h;
        UNPK(p0l, p0h, acc[0][oi]);
        UNPK(p1l, p1h, acc[1][oi]);
        float v0 = lrelu(p0l + bv), v1 = lrelu(p0h + bv);
        float v2 = lrelu(p1l + bv), v3 = lrelu(p1h + bv);
        ((float4*)(g_y3 + ((size_t)o * 48 + loc) * B_TOTAL + B0))[sg] =
            make_float4(v0, v1, v2, v3);
        float s = wsum(v0 + v1 + v2 + v3);
        float qq = wsum(v0 * v0 + v1 * v1 + v2 * v2 + v3 * v3);
        if ((t & 31) == 0) {
            atomicAdd(&red[o * 2 + 0], s);
            atomicAdd(&red[o * 2 + 1], qq);
        }
    }
    __syncthreads();
    if (t < 16) g_part3[(blockIdx.y * 48 + loc) * 16 + t] = red[t];
}

// ============================ stat reducer ====================================
__global__ void kred(int stage, int nb, int nch, float invN,
                     const float* __restrict__ gamma, const float* __restrict__ beta) {
    __shared__ float sm[1024];
    const float* part = (stage == 0) ? g_part1 : (stage == 1) ? g_part2 : g_part3;
    float* bnA = (stage == 0) ? g_bnA1 : (stage == 1) ? g_bnA2 : g_bnA3;
    float* bnB = (stage == 0) ? g_bnB1 : (stage == 1) ? g_bnB2 : g_bnB3;
    const int t = threadIdx.x;
    const int slots = 2 * nch;
    const int grp = t % slots;
    const int lane = t / slots;
    const int per = blockDim.x / slots;
    float s = 0.f;
    for (int i = lane; i < nb; i += per) s += part[i * slots + grp];
    sm[t] = s;
    __syncthreads();
    for (int step = per >> 1; step > 0; step >>= 1) {
        if (lane < step) sm[t] += sm[t + step * slots];
        __syncthreads();
    }
    if (t < nch) {
        float sum = sm[t * 2 + 0], sq = sm[t * 2 + 1];
        float mean = sum * invN;
        float var = sq * invN - mean * mean;
        float rs = rsqrtf(var + BN_EPS);
        float g = gamma[t];
        bnA[t] = g * rs;
        bnB[t] = beta[t] - mean * g * rs;
    }
}

// ============================ K7: BN3 + transpose to output ===================
__global__ void k7_out(float* __restrict__ out) {
    __shared__ float tile[32][65];
    __shared__ float a3[8], b3[8];
    const int t  = threadIdx.x;
    const int f0 = blockIdx.x * 32;
    const int b0 = blockIdx.y * 64;
    if (t < 8) { a3[t] = g_bnA3[t]; b3[t] = g_bnB3[t]; }
    __syncthreads();
#pragma unroll
    for (int r = 0; r < 8; ++r) {
        int f = r * 4 + (t >> 6);
        int b = t & 63;
        float v = g_y3[(size_t)(f0 + f) * B_TOTAL + b0 + b];
        int c = (f0 + f) / 48;
        tile[f][b] = fmaf(a3[c], v, b3[c]);
    }
    __syncthreads();
#pragma unroll
    for (int r = 0; r < 8; ++r) {
        int f = t & 31;
        int b = r * 8 + (t >> 5);
        out[(size_t)(b0 + b) * 384 + f0 + f] = tile[f][b];
    }
}

// ============================ launch ==========================================
extern "C" void kernel_launch(void* const* d_in, const int* in_sizes, int n_in,
                              void* d_out, int out_size) {
    const float* image = (const float*)d_in[0];
    const float* c1w   = (const float*)d_in[1];
    const float* c1b   = (const float*)d_in[2];
    const float* lc1w  = (const float*)d_in[3];
    const float* lc1b  = (const float*)d_in[4];
    const float* lc2w  = (const float*)d_in[5];
    const float* lc2b  = (const float*)d_in[6];
    const float* lc3w  = (const float*)d_in[7];
    const float* lc3b  = (const float*)d_in[8];
    const float* g1    = (const float*)d_in[9];
    const float* be1   = (const float*)d_in[10];
    const float* g2    = (const float*)d_in[11];
    const float* be2   = (const float*)d_in[12];
    const float* g3    = (const float*)d_in[13];
    const float* be3   = (const float*)d_in[14];
    float* out = (float*)d_out;

    cudaFuncSetAttribute(k0_conv1, cudaFuncAttributeMaxDynamicSharedMemorySize, SMEM0);
    cudaFuncSetAttribute(k1_lc1,   cudaFuncAttributeMaxDynamicSharedMemorySize, SMEM1);
    cudaFuncSetAttribute(k3_lc2,   cudaFuncAttributeMaxDynamicSharedMemorySize, SMEM3);
    cudaFuncSetAttribute(k5_lc3,   cudaFuncAttributeMaxDynamicSharedMemorySize, SMEM5);

    k0_conv1<<<dim3(32, 8),   256, SMEM0>>>(image, c1w, c1b);
    k1_lc1  <<<dim3(50, 16),  256, SMEM1>>>(lc1w, lc1b);
    kred    <<<1, 1024>>>(0, 800,  16, 1.0f / (8192.0f * 50.0f), g1, be1);
    k3_lc2  <<<dim3(66, 16),  256, SMEM3>>>(lc2w, lc2b);
    kred    <<<1, 1024>>>(1, 1056, 8,  1.0f / (8192.0f * 66.0f), g2, be2);
    k5_lc3  <<<dim3(48, 16),  256, SMEM5>>>(lc3w, lc3b);
    kred    <<<1, 1024>>>(2, 768,  8,  1.0f / (8192.0f * 48.0f), g3, be3);
    k7_out  <<<dim3(12, 128), 256>>>(out);
}

// round 3
// speedup vs baseline: 1.3987x; 1.3811x over previous
#include <cuda_runtime.h>
#include <cstdint>

#define B_TOTAL   8192
#define LEAK      0.01f
#define BN_EPS    1e-5f

// -------------------- global scratch (allocation-free rule) --------------------
__device__ float g_conv[64 * 90 * B_TOTAL];   // conv1 out, unpadded [64][10][9][B]
__device__ float g_y1[16 * 50 * B_TOTAL];
__device__ float g_y2[8 * 66 * B_TOTAL];
__device__ float g_y3[8 * 48 * B_TOTAL];
__device__ float g_part1[800 * 32];
__device__ float g_part2[528 * 16];
__device__ float g_part3[384 * 16];
__device__ float g_bnA1[16], g_bnB1[16];
__device__ float g_bnA2[8],  g_bnB2[8];
__device__ float g_bnA3[8],  g_bnB3[8];

typedef unsigned long long u64;

__device__ __forceinline__ float lrelu(float v) { return v < 0.f ? LEAK * v : v; }
__device__ __forceinline__ float wsum(float v) {
#pragma unroll
    for (int s = 16; s; s >>= 1) v += __shfl_xor_sync(0xffffffffu, v, s);
    return v;
}
__device__ __forceinline__ u64 dup2f(float v) {
    u64 r; asm("mov.b64 %0, {%1, %1};" : "=l"(r) : "f"(v)); return r;
}
#define FMA2(d, a, b)     asm("fma.rn.f32x2 %0, %1, %2, %0;" : "+l"(d) : "l"(a), "l"(b))
#define FMA2_3(d, a, b, c) asm("fma.rn.f32x2 %0, %1, %2, %3;" : "=l"(d) : "l"(a), "l"(b), "l"(c))
#define UNPK(lo, hi, v)   asm("mov.b64 {%0, %1}, %2;" : "=f"(lo), "=f"(hi) : "l"(v))

// ============================ K0: conv1 + lrelu ===============================
#define SMEM0 ((256 * 91 + 32 + 8) * 4)
__global__ void k0_conv1(const float* __restrict__ img,
                         const float* __restrict__ w1,
                         const float* __restrict__ b1) {
    extern __shared__ float sm0[];
    float* simg = sm0;                 // [256][91]
    float* sw   = sm0 + 256 * 91;      // [8][4]
    float* sb   = sw + 32;             // [8]
    const int t  = threadIdx.x;
    const int B0 = blockIdx.x * 256;
    const int c0 = blockIdx.y * 8;

#pragma unroll 1
    for (int i = 0; i < 90; ++i) {
        int f = i * 256 + t;
        int s = f / 90, off = f - s * 90;
        simg[s * 91 + off] = img[(B0 + s) * 90 + off];
    }
    if (t < 32) sw[t] = w1[c0 * 4 + t];
    if (t < 8)  sb[t] = b1[c0 + t];
    __syncthreads();

    const int q  = t & 63;
    const int cg = t >> 6;
    float W00[2], W01[2], W10[2], W11[2], BB[2];
#pragma unroll
    for (int c2 = 0; c2 < 2; ++c2) {
        int cc = cg * 2 + c2;
        W00[c2] = sw[cc * 4 + 0]; W01[c2] = sw[cc * 4 + 1];
        W10[c2] = sw[cc * 4 + 2]; W11[c2] = sw[cc * 4 + 3];
        BB[c2]  = sb[cc];
    }

#pragma unroll 1
    for (int h = 0; h < 10; ++h) {
        float a[4][9], b[4][9];
        const bool hb = (h < 9);
#pragma unroll
        for (int s = 0; s < 4; ++s) {
            const float* rp = simg + (q * 4 + s) * 91 + h * 9;
#pragma unroll
            for (int w = 0; w < 9; ++w) {
                a[s][w] = rp[w];
                b[s][w] = hb ? rp[9 + w] : 0.f;
            }
        }
#pragma unroll
        for (int c2 = 0; c2 < 2; ++c2) {
            const int c = c0 + cg * 2 + c2;
            float* op = g_conv + ((size_t)c * 90 + h * 9) * B_TOTAL + B0 + q * 4;
            const float w00 = W00[c2], w01 = W01[c2], w10 = W10[c2], w11 = W11[c2], bv = BB[c2];
#pragma unroll
            for (int w = 0; w < 9; ++w) {
                float v[4];
#pragma unroll
                for (int s = 0; s < 4; ++s) {
                    float t0 = fmaf(a[s][w], w00, bv);
                    if (w < 8) t0 = fmaf(a[s][w + 1], w01, t0);
                    t0 = fmaf(b[s][w], w10, t0);
                    if (w < 8) t0 = fmaf(b[s][w + 1], w11, t0);
                    v[s] = lrelu(t0);
                }
                ((float4*)(op + (size_t)w * B_TOTAL))[0] = make_float4(v[0], v[1], v[2], v[3]);
            }
        }
    }
}

// ============================ K1: LC1 direct-global GEMM =====================
// grid (50, 16), block 256. Thread: 2 samples x 16 channels. 512 samples/block.
// Channel-paired f32x2: acc0[j] = (ch 2j,2j+1) sample0; acc1[j] = sample1.
__global__ void __launch_bounds__(256) k1_lc1(const float* __restrict__ lcw,
                                              const float* __restrict__ lcb) {
    __shared__ __align__(16) float Wsm[9216];   // [576][16]
    __shared__ int soff[580];
    __shared__ float red[32];
    const int t   = threadIdx.x;
    const int loc = blockIdx.x;
    const int B0  = blockIdx.y * 512;
    const int h   = loc / 5, w = loc - h * 5;

#pragma unroll
    for (int rr = 0; rr < 4; ++rr) {
        int rid = rr * 256 + t;
        int o = rid >> 6, c = rid & 63;
        const float* src = lcw + ((size_t)(o * 64 + c) * 50 + loc) * 9;
#pragma unroll
        for (int m = 0; m < 9; ++m) Wsm[(c * 9 + m) * 16 + o] = src[m];
    }
    for (int k = t; k < 580; k += 256) {
        int v = -1;
        if (k < 576) {
            int c = k / 9, m = k - 9 * c, i3 = m / 3, j3 = m - 3 * i3;
            int r = h + i3, cc = 2 * w + j3;
            if (r >= 1 && r <= 10 && cc >= 1 && cc <= 9)
                v = ((c * 10 + r - 1) * 9 + cc - 1) * B_TOTAL;
        }
        soff[k] = v;
    }
    if (t < 32) red[t] = 0.f;
    __syncthreads();

    const float* gA = g_conv + B0 + t * 2;
    u64 acc0[8] = {}, acc1[8] = {};
    const ulonglong2* Wv = (const ulonglong2*)Wsm;

    float2 p0, p1;
    { int o = soff[0]; p0 = make_float2(0.f, 0.f); if (o >= 0) p0 = *(const float2*)(gA + o); }
    { int o = soff[1]; p1 = make_float2(0.f, 0.f); if (o >= 0) p1 = *(const float2*)(gA + o); }

#pragma unroll 4
    for (int k = 0; k < 576; ++k) {
        float2 cur = p0; p0 = p1;
        { int o = soff[k + 2]; p1 = make_float2(0.f, 0.f); if (o >= 0) p1 = *(const float2*)(gA + o); }
        u64 s0 = dup2f(cur.x), s1 = dup2f(cur.y);
        ulonglong2 wA = Wv[k * 4 + 0], wB = Wv[k * 4 + 1];
        ulonglong2 wC = Wv[k * 4 + 2], wD = Wv[k * 4 + 3];
        FMA2(acc0[0], s0, wA.x); FMA2(acc0[1], s0, wA.y);
        FMA2(acc0[2], s0, wB.x); FMA2(acc0[3], s0, wB.y);
        FMA2(acc0[4], s0, wC.x); FMA2(acc0[5], s0, wC.y);
        FMA2(acc0[6], s0, wD.x); FMA2(acc0[7], s0, wD.y);
        FMA2(acc1[0], s1, wA.x); FMA2(acc1[1], s1, wA.y);
        FMA2(acc1[2], s1, wB.x); FMA2(acc1[3], s1, wB.y);
        FMA2(acc1[4], s1, wC.x); FMA2(acc1[5], s1, wC.y);
        FMA2(acc1[6], s1, wD.x); FMA2(acc1[7], s1, wD.y);
    }

#pragma unroll
    for (int j = 0; j < 8; ++j) {
        const float b0v = lcb[(2 * j) * 50 + loc];
        const float b1v = lcb[(2 * j + 1) * 50 + loc];
        float xlo, xhi, ylo, yhi;
        UNPK(xlo, xhi, acc0[j]);   // sample0: ch 2j (lo), 2j+1 (hi)
        UNPK(ylo, yhi, acc1[j]);   // sample1
        float v00 = lrelu(xlo + b0v), v01 = lrelu(ylo + b0v);
        float v10 = lrelu(xhi + b1v), v11 = lrelu(yhi + b1v);
        ((float2*)(g_y1 + ((size_t)(2 * j) * 50 + loc) * B_TOTAL + B0))[t] = make_float2(v00, v01);
        ((float2*)(g_y1 + ((size_t)(2 * j + 1) * 50 + loc) * B_TOTAL + B0))[t] = make_float2(v10, v11);
        float s0s = wsum(v00 + v01), q0 = wsum(v00 * v00 + v01 * v01);
        float s1s = wsum(v10 + v11), q1 = wsum(v10 * v10 + v11 * v11);
        if ((t & 31) == 0) {
            atomicAdd(&red[(2 * j) * 2 + 0], s0s);     atomicAdd(&red[(2 * j) * 2 + 1], q0);
            atomicAdd(&red[(2 * j + 1) * 2 + 0], s1s); atomicAdd(&red[(2 * j + 1) * 2 + 1], q1);
        }
    }
    __syncthreads();
    if (t < 32) g_part1[(blockIdx.y * 50 + loc) * 32 + t] = red[t];
}

// ============================ K3: BN1 + pad + LC2 direct =====================
// grid (66, 8), block 256. Thread: 4 samples x 8 channels. 1024 samples/block.
// Sample-paired f32x2, dup'd W in smem, BN fused into fetch.
#define K3_FETCH(d0, d1, kk) do {                                            \
    int _o = soff[kk]; d0 = 0ULL; d1 = 0ULL;                                 \
    if (_o >= 0) {                                                           \
        ulonglong2 _y = *(const ulonglong2*)(gA + _o);                       \
        int _c = (kk) >> 2;                                                  \
        u64 _a = bnAd[_c], _b = bnBd[_c];                                    \
        FMA2_3(d0, _y.x, _a, _b); FMA2_3(d1, _y.y, _a, _b);                  \
    } } while (0)

__global__ void __launch_bounds__(256) k3_lc2(const float* __restrict__ lcw,
                                              const float* __restrict__ lcb) {
    __shared__ __align__(16) u64 Wd[512];       // [64][8] dup'd
    __shared__ u64 bnAd[16], bnBd[16];
    __shared__ int soff[68];
    __shared__ float red[16];
    const int t   = threadIdx.x;
    const int loc = blockIdx.x;
    const int B0  = blockIdx.y * 1024;
    const int h2  = loc / 6, w2 = loc - h2 * 6;

    if (t < 16) { bnAd[t] = dup2f(g_bnA1[t]); bnBd[t] = dup2f(g_bnB1[t]); red[t] = 0.f; }
#pragma unroll
    for (int rr = 0; rr < 2; ++rr) {
        int idx = rr * 256 + t;                 // k*8 + o
        int o = idx & 7, k = idx >> 3;
        int c = k >> 2, m = k & 3;
        Wd[idx] = dup2f(lcw[(size_t)((o * 16 + c) * 66 + loc) * 4 + m]);
    }
    for (int k = t; k < 68; k += 256) {
        int v = -1;
        if (k < 64) {
            int c = k >> 2, m = k & 3;
            int hp = h2 + (m >> 1), wp = w2 + (m & 1);
            if (hp >= 1 && hp <= 10 && wp >= 1 && wp <= 5)
                v = (c * 50 + (hp - 1) * 5 + (wp - 1)) * B_TOTAL;
        }
        soff[k] = v;
    }
    __syncthreads();

    const float* gA = g_y1 + B0 + t * 4;
    u64 acc[2][8] = {};
    u64 f00, f01, f10, f11;
    K3_FETCH(f00, f01, 0);
    K3_FETCH(f10, f11, 1);

#pragma unroll 4
    for (int k = 0; k < 64; ++k) {
        u64 a0 = f00, a1 = f01;
        f00 = f10; f01 = f11;
        K3_FETCH(f10, f11, k + 2);
        const ulonglong2* wp = (const ulonglong2*)(Wd + k * 8);
        ulonglong2 wA = wp[0], wB = wp[1], wC = wp[2], wD = wp[3];
        FMA2(acc[0][0], a0, wA.x); FMA2(acc[0][1], a0, wA.y);
        FMA2(acc[0][2], a0, wB.x); FMA2(acc[0][3], a0, wB.y);
        FMA2(acc[0][4], a0, wC.x); FMA2(acc[0][5], a0, wC.y);
        FMA2(acc[0][6], a0, wD.x); FMA2(acc[0][7], a0, wD.y);
        FMA2(acc[1][0], a1, wA.x); FMA2(acc[1][1], a1, wA.y);
        FMA2(acc[1][2], a1, wB.x); FMA2(acc[1][3], a1, wB.y);
        FMA2(acc[1][4], a1, wC.x); FMA2(acc[1][5], a1, wC.y);
        FMA2(acc[1][6], a1, wD.x); FMA2(acc[1][7], a1, wD.y);
    }

#pragma unroll
    for (int o = 0; o < 8; ++o) {
        const float bv = lcb[o * 66 + loc];
        float v0, v1, v2, v3;
        UNPK(v0, v1, acc[0][o]);
        UNPK(v2, v3, acc[1][o]);
        v0 = lrelu(v0 + bv); v1 = lrelu(v1 + bv);
        v2 = lrelu(v2 + bv); v3 = lrelu(v3 + bv);
        ((float4*)(g_y2 + ((size_t)o * 66 + loc) * B_TOTAL + B0))[t] =
            make_float4(v0, v1, v2, v3);
        float s = wsum(v0 + v1 + v2 + v3);
        float q = wsum(v0 * v0 + v1 * v1 + v2 * v2 + v3 * v3);
        if ((t & 31) == 0) {
            atomicAdd(&red[o * 2 + 0], s);
            atomicAdd(&red[o * 2 + 1], q);
        }
    }
    __syncthreads();
    if (t < 16) g_part2[(blockIdx.y * 66 + loc) * 16 + t] = red[t];
}

// ============================ K5: BN2 + pad + LC3 direct =====================
// grid (48, 8), block 256. Thread: 4 samples x 8 channels.
__global__ void __launch_bounds__(256) k5_lc3(const float* __restrict__ lcw,
                                              const float* __restrict__ lcb) {
    __shared__ __align__(16) u64 Wd[256];       // [32][8] dup'd
    __shared__ u64 bnAd[8], bnBd[8];
    __shared__ int soff[36];
    __shared__ float red[16];
    const int t   = threadIdx.x;
    const int loc = blockIdx.x;
    const int B0  = blockIdx.y * 1024;
    const int h3  = loc >> 2, w3 = loc & 3;

    if (t < 8)  { bnAd[t] = dup2f(g_bnA2[t]); bnBd[t] = dup2f(g_bnB2[t]); }
    if (t < 16) red[t] = 0.f;
    if (t < 256) {
        int o = t & 7, k = t >> 3;
        int c = k >> 2, m = k & 3;
        Wd[t] = dup2f(lcw[(size_t)((o * 8 + c) * 48 + loc) * 4 + m]);
    }
    for (int k = t; k < 36; k += 256) {
        int v = -1;
        if (k < 32) {
            int c = k >> 2, m = k & 3;
            int hp = h3 + (m >> 1), wp = 2 * w3 + (m & 1);
            if (hp >= 1 && hp <= 11 && wp >= 1 && wp <= 6)
                v = (c * 66 + (hp - 1) * 6 + (wp - 1)) * B_TOTAL;
        }
        soff[k] = v;
    }
    __syncthreads();

    const float* gA = g_y2 + B0 + t * 4;
    u64 acc[2][8] = {};
    u64 f00, f01, f10, f11;
    K3_FETCH(f00, f01, 0);
    K3_FETCH(f10, f11, 1);

#pragma unroll 4
    for (int k = 0; k < 32; ++k) {
        u64 a0 = f00, a1 = f01;
        f00 = f10; f01 = f11;
        K3_FETCH(f10, f11, k + 2);
        const ulonglong2* wp = (const ulonglong2*)(Wd + k * 8);
        ulonglong2 wA = wp[0], wB = wp[1], wC = wp[2], wD = wp[3];
        FMA2(acc[0][0], a0, wA.x); FMA2(acc[0][1], a0, wA.y);
        FMA2(acc[0][2], a0, wB.x); FMA2(acc[0][3], a0, wB.y);
        FMA2(acc[0][4], a0, wC.x); FMA2(acc[0][5], a0, wC.y);
        FMA2(acc[0][6], a0, wD.x); FMA2(acc[0][7], a0, wD.y);
        FMA2(acc[1][0], a1, wA.x); FMA2(acc[1][1], a1, wA.y);
        FMA2(acc[1][2], a1, wB.x); FMA2(acc[1][3], a1, wB.y);
        FMA2(acc[1][4], a1, wC.x); FMA2(acc[1][5], a1, wC.y);
        FMA2(acc[1][6], a1, wD.x); FMA2(acc[1][7], a1, wD.y);
    }

#pragma unroll
    for (int o = 0; o < 8; ++o) {
        const float bv = lcb[o * 48 + loc];
        float v0, v1, v2, v3;
        UNPK(v0, v1, acc[0][o]);
        UNPK(v2, v3, acc[1][o]);
        v0 = lrelu(v0 + bv); v1 = lrelu(v1 + bv);
        v2 = lrelu(v2 + bv); v3 = lrelu(v3 + bv);
        ((float4*)(g_y3 + ((size_t)o * 48 + loc) * B_TOTAL + B0))[t] =
            make_float4(v0, v1, v2, v3);
        float s = wsum(v0 + v1 + v2 + v3);
        float q = wsum(v0 * v0 + v1 * v1 + v2 * v2 + v3 * v3);
        if ((t & 31) == 0) {
            atomicAdd(&red[o * 2 + 0], s);
            atomicAdd(&red[o * 2 + 1], q);
        }
    }
    __syncthreads();
    if (t < 16) g_part3[(blockIdx.y * 48 + loc) * 16 + t] = red[t];
}

// ============================ stat reducer ====================================
__global__ void kred(int stage, int nb, int nch, float invN,
                     const float* __restrict__ gamma, const float* __restrict__ beta) {
    __shared__ float sm[1024];
    const float* part = (stage == 0) ? g_part1 : (stage == 1) ? g_part2 : g_part3;
    float* bnA = (stage == 0) ? g_bnA1 : (stage == 1) ? g_bnA2 : g_bnA3;
    float* bnB = (stage == 0) ? g_bnB1 : (stage == 1) ? g_bnB2 : g_bnB3;
    const int t = threadIdx.x;
    const int slots = 2 * nch;
    const int grp = t % slots;
    const int lane = t / slots;
    const int per = blockDim.x / slots;
    float s = 0.f;
    for (int i = lane; i < nb; i += per) s += part[i * slots + grp];
    sm[t] = s;
    __syncthreads();
    for (int step = per >> 1; step > 0; step >>= 1) {
        if (lane < step) sm[t] += sm[t + step * slots];
        __syncthreads();
    }
    if (t < nch) {
        float sum = sm[t * 2 + 0], sq = sm[t * 2 + 1];
        float mean = sum * invN;
        float var = sq * invN - mean * mean;
        float rs = rsqrtf(var + BN_EPS);
        float g = gamma[t];
        bnA[t] = g * rs;
        bnB[t] = beta[t] - mean * g * rs;
    }
}

// ============================ K7: BN3 + transpose to output ===================
__global__ void k7_out(float* __restrict__ out) {
    __shared__ float tile[32][65];
    __shared__ float a3[8], b3[8];
    const int t  = threadIdx.x;
    const int f0 = blockIdx.x * 32;
    const int b0 = blockIdx.y * 64;
    if (t < 8) { a3[t] = g_bnA3[t]; b3[t] = g_bnB3[t]; }
    __syncthreads();
#pragma unroll
    for (int r = 0; r < 8; ++r) {
        int f = r * 4 + (t >> 6);
        int b = t & 63;
        float v = g_y3[(size_t)(f0 + f) * B_TOTAL + b0 + b];
        int c = (f0 + f) / 48;
        tile[f][b] = fmaf(a3[c], v, b3[c]);
    }
    __syncthreads();
#pragma unroll
    for (int r = 0; r < 8; ++r) {
        int f = t & 31;
        int b = r * 8 + (t >> 5);
        out[(size_t)(b0 + b) * 384 + f0 + f] = tile[f][b];
    }
}

// ============================ launch ==========================================
extern "C" void kernel_launch(void* const* d_in, const int* in_sizes, int n_in,
                              void* d_out, int out_size) {
    const float* image = (const float*)d_in[0];
    const float* c1w   = (const float*)d_in[1];
    const float* c1b   = (const float*)d_in[2];
    const float* lc1w  = (const float*)d_in[3];
    const float* lc1b  = (const float*)d_in[4];
    const float* lc2w  = (const float*)d_in[5];
    const float* lc2b  = (const float*)d_in[6];
    const float* lc3w  = (const float*)d_in[7];
    const float* lc3b  = (const float*)d_in[8];
    const float* g1    = (const float*)d_in[9];
    const float* be1   = (const float*)d_in[10];
    const float* g2    = (const float*)d_in[11];
    const float* be2   = (const float*)d_in[12];
    const float* g3    = (const float*)d_in[13];
    const float* be3   = (const float*)d_in[14];
    float* out = (float*)d_out;

    cudaFuncSetAttribute(k0_conv1, cudaFuncAttributeMaxDynamicSharedMemorySize, SMEM0);

    k0_conv1<<<dim3(32, 8),   256, SMEM0>>>(image, c1w, c1b);
    k1_lc1  <<<dim3(50, 16),  256>>>(lc1w, lc1b);
    kred    <<<1, 1024>>>(0, 800, 16, 1.0f / (8192.0f * 50.0f), g1, be1);
    k3_lc2  <<<dim3(66, 8),   256>>>(lc2w, lc2b);
    kred    <<<1, 1024>>>(1, 528, 8,  1.0f / (8192.0f * 66.0f), g2, be2);
    k5_lc3  <<<dim3(48, 8),   256>>>(lc3w, lc3b);
    kred    <<<1, 1024>>>(2, 384, 8,  1.0f / (8192.0f * 48.0f), g3, be3);
    k7_out  <<<dim3(12, 128), 256>>>(out);
}

// round 4
// speedup vs baseline: 1.6572x; 1.1848x over previous
#include <cuda_runtime.h>
#include <cstdint>

#define B_TOTAL   8192
#define LEAK      0.01f
#define BN_EPS    1e-5f

// -------------------- global scratch --------------------
__device__ float g_conv[64 * 90 * B_TOTAL];   // conv1 out [64][10][9][B]
__device__ float g_y1[16 * 50 * B_TOTAL];
__device__ float g_y2[8 * 66 * B_TOTAL];
__device__ float g_y3[8 * 48 * B_TOTAL];
__device__ float g_part1[400 * 32];
__device__ float g_part2[528 * 16];
__device__ float g_part3[384 * 16];
__device__ float g_bnA1[16], g_bnB1[16];
__device__ float g_bnA2[8],  g_bnB2[8];
__device__ float g_bnA3[8],  g_bnB3[8];

typedef unsigned long long u64;

__device__ __forceinline__ float lrelu(float v) { return v < 0.f ? LEAK * v : v; }
__device__ __forceinline__ float wsum(float v) {
#pragma unroll
    for (int s = 16; s; s >>= 1) v += __shfl_xor_sync(0xffffffffu, v, s);
    return v;
}
__device__ __forceinline__ u64 dup2f(float v) {
    u64 r; asm("mov.b64 %0, {%1, %1};" : "=l"(r) : "f"(v)); return r;
}
#define FMA2(d, a, b)   asm("fma.rn.f32x2 %0, %1, %2, %0;" : "+l"(d) : "l"(a), "l"(b))
#define UNPK(lo, hi, v) asm("mov.b64 {%0, %1}, %2;" : "=f"(lo), "=f"(hi) : "l"(v))

// 8-channel FMA2 burst against dup/paired weight regs wA..wD
#define CH8(ar, s)                                              \
    FMA2(ar[0], s, wA.x); FMA2(ar[1], s, wA.y);                 \
    FMA2(ar[2], s, wB.x); FMA2(ar[3], s, wB.y);                 \
    FMA2(ar[4], s, wC.x); FMA2(ar[5], s, wC.y);                 \
    FMA2(ar[6], s, wD.x); FMA2(ar[7], s, wD.y);

// ============================ K0: conv1 + lrelu ===============================
#define SMEM0 ((256 * 91 + 32 + 8) * 4)
__global__ void k0_conv1(const float* __restrict__ img,
                         const float* __restrict__ w1,
                         const float* __restrict__ b1) {
    extern __shared__ float sm0[];
    float* simg = sm0;
    float* sw   = sm0 + 256 * 91;
    float* sb   = sw + 32;
    const int t  = threadIdx.x;
    const int B0 = blockIdx.x * 256;
    const int c0 = blockIdx.y * 8;

#pragma unroll 1
    for (int i = 0; i < 90; ++i) {
        int f = i * 256 + t;
        int s = f / 90, off = f - s * 90;
        simg[s * 91 + off] = img[(B0 + s) * 90 + off];
    }
    if (t < 32) sw[t] = w1[c0 * 4 + t];
    if (t < 8)  sb[t] = b1[c0 + t];
    __syncthreads();

    const int q  = t & 63;
    const int cg = t >> 6;
    float W00[2], W01[2], W10[2], W11[2], BB[2];
#pragma unroll
    for (int c2 = 0; c2 < 2; ++c2) {
        int cc = cg * 2 + c2;
        W00[c2] = sw[cc * 4 + 0]; W01[c2] = sw[cc * 4 + 1];
        W10[c2] = sw[cc * 4 + 2]; W11[c2] = sw[cc * 4 + 3];
        BB[c2]  = sb[cc];
    }

#pragma unroll 1
    for (int h = 0; h < 10; ++h) {
        float a[4][9], b[4][9];
        const bool hb = (h < 9);
#pragma unroll
        for (int s = 0; s < 4; ++s) {
            const float* rp = simg + (q * 4 + s) * 91 + h * 9;
#pragma unroll
            for (int w = 0; w < 9; ++w) {
                a[s][w] = rp[w];
                b[s][w] = hb ? rp[9 + w] : 0.f;
            }
        }
#pragma unroll
        for (int c2 = 0; c2 < 2; ++c2) {
            const int c = c0 + cg * 2 + c2;
            float* op = g_conv + ((size_t)c * 90 + h * 9) * B_TOTAL + B0 + q * 4;
            const float w00 = W00[c2], w01 = W01[c2], w10 = W10[c2], w11 = W11[c2], bv = BB[c2];
#pragma unroll
            for (int w = 0; w < 9; ++w) {
                float v[4];
#pragma unroll
                for (int s = 0; s < 4; ++s) {
                    float t0 = fmaf(a[s][w], w00, bv);
                    if (w < 8) t0 = fmaf(a[s][w + 1], w01, t0);
                    t0 = fmaf(b[s][w], w10, t0);
                    if (w < 8) t0 = fmaf(b[s][w + 1], w11, t0);
                    v[s] = lrelu(t0);
                }
                ((float4*)(op + (size_t)w * B_TOTAL))[0] = make_float4(v[0], v[1], v[2], v[3]);
            }
        }
    }
}

// ============================ K1: LC1 direct-global GEMM =====================
// grid (50, 8), block 256. Thread: 4 samples x 16 channels (channel-paired f32x2).
#define K1_BODY(PF, KIDX) do {                                               \
    float4 cur = PF;                                                         \
    { int _o = soff[(KIDX) + 3];                                             \
      PF = make_float4(0.f, 0.f, 0.f, 0.f);                                  \
      if (_o >= 0) PF = *(const float4*)(gA + _o); }                         \
    u64 s0 = dup2f(cur.x), s1 = dup2f(cur.y);                                \
    u64 s2 = dup2f(cur.z), s3 = dup2f(cur.w);                                \
    const ulonglong2* wp = Wv + (size_t)(KIDX) * 4;                          \
    ulonglong2 wA = wp[0], wB = wp[1], wC = wp[2], wD = wp[3];               \
    CH8(acc[0], s0); CH8(acc[1], s1); CH8(acc[2], s2); CH8(acc[3], s3);      \
} while (0)

__global__ void __launch_bounds__(256, 2) k1_lc1(const float* __restrict__ lcw,
                                                 const float* __restrict__ lcb) {
    __shared__ __align__(16) float Wsm[9216];   // [576][16]
    __shared__ int soff[592];
    __shared__ float red[32];
    const int t   = threadIdx.x;
    const int loc = blockIdx.x;
    const int B0  = blockIdx.y * 1024;
    const int h   = loc / 5, w = loc - h * 5;

#pragma unroll
    for (int rr = 0; rr < 4; ++rr) {
        int rid = rr * 256 + t;
        int o = rid >> 6, c = rid & 63;
        const float* src = lcw + ((size_t)(o * 64 + c) * 50 + loc) * 9;
#pragma unroll
        for (int m = 0; m < 9; ++m) Wsm[(c * 9 + m) * 16 + o] = src[m];
    }
    for (int k = t; k < 592; k += 256) {
        int v = -1;
        if (k < 576) {
            int c = k / 9, m = k - 9 * c, i3 = m / 3, j3 = m - 3 * i3;
            int r = h + i3, cc = 2 * w + j3;
            if (r >= 1 && r <= 10 && cc >= 1 && cc <= 9)
                v = ((c * 10 + r - 1) * 9 + cc - 1) * B_TOTAL;
        }
        soff[k] = v;
    }
    if (t < 32) red[t] = 0.f;
    __syncthreads();

    const float* gA = g_conv + B0 + t * 4;
    const ulonglong2* Wv = (const ulonglong2*)Wsm;
    u64 acc[4][8] = {};

    float4 pf0, pf1, pf2;
    { int o = soff[0]; pf0 = make_float4(0.f,0.f,0.f,0.f); if (o >= 0) pf0 = *(const float4*)(gA + o); }
    { int o = soff[1]; pf1 = make_float4(0.f,0.f,0.f,0.f); if (o >= 0) pf1 = *(const float4*)(gA + o); }
    { int o = soff[2]; pf2 = make_float4(0.f,0.f,0.f,0.f); if (o >= 0) pf2 = *(const float4*)(gA + o); }

#pragma unroll 3
    for (int k = 0; k < 576; k += 3) {
        K1_BODY(pf0, k);
        K1_BODY(pf1, k + 1);
        K1_BODY(pf2, k + 2);
    }

    // epilogue: bias + lrelu + store + stats
#pragma unroll
    for (int j = 0; j < 8; ++j) {
        const int o0 = 2 * j, o1 = 2 * j + 1;
        const float b0v = lcb[o0 * 50 + loc];
        const float b1v = lcb[o1 * 50 + loc];
        float lo[4], hi[4];
#pragma unroll
        for (int s = 0; s < 4; ++s) UNPK(lo[s], hi[s], acc[s][j]);
        float a0 = lrelu(lo[0] + b0v), a1 = lrelu(lo[1] + b0v);
        float a2 = lrelu(lo[2] + b0v), a3 = lrelu(lo[3] + b0v);
        float c0 = lrelu(hi[0] + b1v), c1 = lrelu(hi[1] + b1v);
        float c2 = lrelu(hi[2] + b1v), c3 = lrelu(hi[3] + b1v);
        ((float4*)(g_y1 + ((size_t)o0 * 50 + loc) * B_TOTAL + B0))[t] = make_float4(a0, a1, a2, a3);
        ((float4*)(g_y1 + ((size_t)o1 * 50 + loc) * B_TOTAL + B0))[t] = make_float4(c0, c1, c2, c3);
        float s0 = wsum(a0 + a1 + a2 + a3), q0 = wsum(a0*a0 + a1*a1 + a2*a2 + a3*a3);
        float s1 = wsum(c0 + c1 + c2 + c3), q1 = wsum(c0*c0 + c1*c1 + c2*c2 + c3*c3);
        if ((t & 31) == 0) {
            atomicAdd(&red[o0 * 2 + 0], s0); atomicAdd(&red[o0 * 2 + 1], q0);
            atomicAdd(&red[o1 * 2 + 0], s1); atomicAdd(&red[o1 * 2 + 1], q1);
        }
    }
    __syncthreads();
    if (t < 32) g_part1[(blockIdx.y * 50 + loc) * 32 + t] = red[t];
}

// ============================ K3/K5 common body ===============================
// 8 samples/thread as 4 natural f32x2 pairs; weights BN-scaled + dup'd in smem.
#define LC_BODY(FA, FB, KIDX) do {                                           \
    ulonglong2 a01 = FA, a23 = FB;                                           \
    { int _o = soff[(KIDX) + 2];                                             \
      FA.x = 0ULL; FA.y = 0ULL; FB.x = 0ULL; FB.y = 0ULL;                    \
      if (_o >= 0) {                                                         \
          const ulonglong2* _p = (const ulonglong2*)(gA + _o);               \
          FA = _p[0]; FB = _p[1];                                            \
      } }                                                                    \
    const ulonglong2* wp = (const ulonglong2*)(Wd + (size_t)(KIDX) * 8);     \
    ulonglong2 wA = wp[0], wB = wp[1], wC = wp[2], wD = wp[3];               \
    CH8(acc[0], a01.x); CH8(acc[1], a01.y);                                  \
    CH8(acc[2], a23.x); CH8(acc[3], a23.y);                                  \
} while (0)

// ============================ K3: BN1(folded) + pad + LC2 =====================
// grid (66, 8), block 128. Thread: 8 samples x 8 channels.
__global__ void __launch_bounds__(128, 4) k3_lc2(const float* __restrict__ lcw,
                                                 const float* __restrict__ lcb) {
    __shared__ __align__(16) u64 Wd[512];       // [64][8] dup'd, scaled by bnA
    __shared__ float biasc[8];
    __shared__ int soff[68];
    __shared__ float red[16];
    const int t   = threadIdx.x;
    const int loc = blockIdx.x;
    const int B0  = blockIdx.y * 1024;
    const int h2  = loc / 6, w2 = loc - h2 * 6;

#pragma unroll
    for (int rr = 0; rr < 4; ++rr) {
        int idx = rr * 128 + t;                 // k*8 + o
        int o = idx & 7, k = idx >> 3;
        int c = k >> 2;
        float wv = lcw[(size_t)((o * 16 + c) * 66 + loc) * 4 + (k & 3)];
        Wd[idx] = dup2f(wv * g_bnA1[c]);
    }
    for (int k = t; k < 68; k += 128) {
        int v = -1;
        if (k < 64) {
            int c = k >> 2, m = k & 3;
            int hp = h2 + (m >> 1), wp = w2 + (m & 1);
            if (hp >= 1 && hp <= 10 && wp >= 1 && wp <= 5)
                v = (c * 50 + (hp - 1) * 5 + (wp - 1)) * B_TOTAL;
        }
        soff[k] = v;
    }
    if (t < 16) red[t] = 0.f;
    if (t < 8) {
        float s = 0.f;
#pragma unroll 1
        for (int k = 0; k < 64; ++k) {
            int c = k >> 2, m = k & 3;
            int hp = h2 + (m >> 1), wp = w2 + (m & 1);
            if (hp >= 1 && hp <= 10 && wp >= 1 && wp <= 5)
                s += lcw[(size_t)((t * 16 + c) * 66 + loc) * 4 + m] * g_bnB1[c];
        }
        biasc[t] = s;
    }
    __syncthreads();

    const float* gA = g_y1 + B0 + t * 8;
    u64 acc[4][8] = {};
    ulonglong2 f0a, f0b, f1a, f1b;
    { int o = soff[0]; f0a.x=f0a.y=f0b.x=f0b.y=0ULL;
      if (o >= 0) { const ulonglong2* p = (const ulonglong2*)(gA + o); f0a = p[0]; f0b = p[1]; } }
    { int o = soff[1]; f1a.x=f1a.y=f1b.x=f1b.y=0ULL;
      if (o >= 0) { const ulonglong2* p = (const ulonglong2*)(gA + o); f1a = p[0]; f1b = p[1]; } }

#pragma unroll 2
    for (int k = 0; k < 64; k += 2) {
        LC_BODY(f0a, f0b, k);
        LC_BODY(f1a, f1b, k + 1);
    }

#pragma unroll
    for (int o = 0; o < 8; ++o) {
        const float bv = lcb[o * 66 + loc] + biasc[o];
        float v[8];
#pragma unroll
        for (int p = 0; p < 4; ++p) UNPK(v[2 * p], v[2 * p + 1], acc[p][o]);
#pragma unroll
        for (int p = 0; p < 8; ++p) v[p] = lrelu(v[p] + bv);
        float* dst = g_y2 + ((size_t)o * 66 + loc) * B_TOTAL + B0 + t * 8;
        ((float4*)dst)[0] = make_float4(v[0], v[1], v[2], v[3]);
        ((float4*)dst)[1] = make_float4(v[4], v[5], v[6], v[7]);
        float s = wsum(v[0]+v[1]+v[2]+v[3]+v[4]+v[5]+v[6]+v[7]);
        float q = wsum(v[0]*v[0]+v[1]*v[1]+v[2]*v[2]+v[3]*v[3]
                     + v[4]*v[4]+v[5]*v[5]+v[6]*v[6]+v[7]*v[7]);
        if ((t & 31) == 0) {
            atomicAdd(&red[o * 2 + 0], s);
            atomicAdd(&red[o * 2 + 1], q);
        }
    }
    __syncthreads();
    if (t < 16) g_part2[(blockIdx.y * 66 + loc) * 16 + t] = red[t];
}

// ============================ K5: BN2(folded) + pad + LC3 =====================
// grid (48, 8), block 128. Thread: 8 samples x 8 channels.
__global__ void __launch_bounds__(128, 4) k5_lc3(const float* __restrict__ lcw,
                                                 const float* __restrict__ lcb) {
    __shared__ __align__(16) u64 Wd[256];       // [32][8] dup'd, scaled by bnA
    __shared__ float biasc[8];
    __shared__ int soff[36];
    __shared__ float red[16];
    const int t   = threadIdx.x;
    const int loc = blockIdx.x;
    const int B0  = blockIdx.y * 1024;
    const int h3  = loc >> 2, w3 = loc & 3;

#pragma unroll
    for (int rr = 0; rr < 2; ++rr) {
        int idx = rr * 128 + t;
        int o = idx & 7, k = idx >> 3;
        int c = k >> 2;
        float wv = lcw[(size_t)((o * 8 + c) * 48 + loc) * 4 + (k & 3)];
        Wd[idx] = dup2f(wv * g_bnA2[c]);
    }
    for (int k = t; k < 36; k += 128) {
        int v = -1;
        if (k < 32) {
            int c = k >> 2, m = k & 3;
            int hp = h3 + (m >> 1), wp = 2 * w3 + (m & 1);
            if (hp >= 1 && hp <= 11 && wp >= 1 && wp <= 6)
                v = (c * 66 + (hp - 1) * 6 + (wp - 1)) * B_TOTAL;
        }
        soff[k] = v;
    }
    if (t < 16) red[t] = 0.f;
    if (t < 8) {
        float s = 0.f;
#pragma unroll 1
        for (int k = 0; k < 32; ++k) {
            int c = k >> 2, m = k & 3;
            int hp = h3 + (m >> 1), wp = 2 * w3 + (m & 1);
            if (hp >= 1 && hp <= 11 && wp >= 1 && wp <= 6)
                s += lcw[(size_t)((t * 8 + c) * 48 + loc) * 4 + m] * g_bnB2[c];
        }
        biasc[t] = s;
    }
    __syncthreads();

    const float* gA = g_y2 + B0 + t * 8;
    u64 acc[4][8] = {};
    ulonglong2 f0a, f0b, f1a, f1b;
    { int o = soff[0]; f0a.x=f0a.y=f0b.x=f0b.y=0ULL;
      if (o >= 0) { const ulonglong2* p = (const ulonglong2*)(gA + o); f0a = p[0]; f0b = p[1]; } }
    { int o = soff[1]; f1a.x=f1a.y=f1b.x=f1b.y=0ULL;
      if (o >= 0) { const ulonglong2* p = (const ulonglong2*)(gA + o); f1a = p[0]; f1b = p[1]; } }

#pragma unroll 2
    for (int k = 0; k < 32; k += 2) {
        LC_BODY(f0a, f0b, k);
        LC_BODY(f1a, f1b, k + 1);
    }

#pragma unroll
    for (int o = 0; o < 8; ++o) {
        const float bv = lcb[o * 48 + loc] + biasc[o];
        float v[8];
#pragma unroll
        for (int p = 0; p < 4; ++p) UNPK(v[2 * p], v[2 * p + 1], acc[p][o]);
#pragma unroll
        for (int p = 0; p < 8; ++p) v[p] = lrelu(v[p] + bv);
        float* dst = g_y3 + ((size_t)o * 48 + loc) * B_TOTAL + B0 + t * 8;
        ((float4*)dst)[0] = make_float4(v[0], v[1], v[2], v[3]);
        ((float4*)dst)[1] = make_float4(v[4], v[5], v[6], v[7]);
        float s = wsum(v[0]+v[1]+v[2]+v[3]+v[4]+v[5]+v[6]+v[7]);
        float q = wsum(v[0]*v[0]+v[1]*v[1]+v[2]*v[2]+v[3]*v[3]
                     + v[4]*v[4]+v[5]*v[5]+v[6]*v[6]+v[7]*v[7]);
        if ((t & 31) == 0) {
            atomicAdd(&red[o * 2 + 0], s);
            atomicAdd(&red[o * 2 + 1], q);
        }
    }
    __syncthreads();
    if (t < 16) g_part3[(blockIdx.y * 48 + loc) * 16 + t] = red[t];
}

// ============================ stat reducer ====================================
__global__ void kred(int stage, int nb, int nch, float invN,
                     const float* __restrict__ gamma, const float* __restrict__ beta) {
    __shared__ float sm[1024];
    const float* part = (stage == 0) ? g_part1 : (stage == 1) ? g_part2 : g_part3;
    float* bnA = (stage == 0) ? g_bnA1 : (stage == 1) ? g_bnA2 : g_bnA3;
    float* bnB = (stage == 0) ? g_bnB1 : (stage == 1) ? g_bnB2 : g_bnB3;
    const int t = threadIdx.x;
    const int slots = 2 * nch;
    const int grp = t % slots;
    const int lane = t / slots;
    const int per = blockDim.x / slots;
    float s = 0.f;
    for (int i = lane; i < nb; i += per) s += part[i * slots + grp];
    sm[t] = s;
    __syncthreads();
    for (int step = per >> 1; step > 0; step >>= 1) {
        if (lane < step) sm[t] += sm[t + step * slots];
        __syncthreads();
    }
    if (t < nch) {
        float sum = sm[t * 2 + 0], sq = sm[t * 2 + 1];
        float mean = sum * invN;
        float var = sq * invN - mean * mean;
        float rs = rsqrtf(var + BN_EPS);
        float g = gamma[t];
        bnA[t] = g * rs;
        bnB[t] = beta[t] - mean * g * rs;
    }
}

// ============================ K7: BN3 + transpose to output ===================
__global__ void k7_out(float* __restrict__ out) {
    __shared__ float tile[32][65];
    __shared__ float a3[8], b3[8];
    const int t  = threadIdx.x;
    const int f0 = blockIdx.x * 32;
    const int b0 = blockIdx.y * 64;
    if (t < 8) { a3[t] = g_bnA3[t]; b3[t] = g_bnB3[t]; }
    __syncthreads();
#pragma unroll
    for (int r = 0; r < 8; ++r) {
        int f = r * 4 + (t >> 6);
        int b = t & 63;
        float v = g_y3[(size_t)(f0 + f) * B_TOTAL + b0 + b];
        int c = (f0 + f) / 48;
        tile[f][b] = fmaf(a3[c], v, b3[c]);
    }
    __syncthreads();
#pragma unroll
    for (int r = 0; r < 8; ++r) {
        int f = t & 31;
        int b = r * 8 + (t >> 5);
        out[(size_t)(b0 + b) * 384 + f0 + f] = tile[f][b];
    }
}

// ============================ launch ==========================================
extern "C" void kernel_launch(void* const* d_in, const int* in_sizes, int n_in,
                              void* d_out, int out_size) {
    const float* image = (const float*)d_in[0];
    const float* c1w   = (const float*)d_in[1];
    const float* c1b   = (const float*)d_in[2];
    const float* lc1w  = (const float*)d_in[3];
    const float* lc1b  = (const float*)d_in[4];
    const float* lc2w  = (const float*)d_in[5];
    const float* lc2b  = (const float*)d_in[6];
    const float* lc3w  = (const float*)d_in[7];
    const float* lc3b  = (const float*)d_in[8];
    const float* g1    = (const float*)d_in[9];
    const float* be1   = (const float*)d_in[10];
    const float* g2    = (const float*)d_in[11];
    const float* be2   = (const float*)d_in[12];
    const float* g3    = (const float*)d_in[13];
    const float* be3   = (const float*)d_in[14];
    float* out = (float*)d_out;

    cudaFuncSetAttribute(k0_conv1, cudaFuncAttributeMaxDynamicSharedMemorySize, SMEM0);

    k0_conv1<<<dim3(32, 8),   256, SMEM0>>>(image, c1w, c1b);
    k1_lc1  <<<dim3(50, 8),   256>>>(lc1w, lc1b);
    kred    <<<1, 1024>>>(0, 400, 16, 1.0f / (8192.0f * 50.0f), g1, be1);
    k3_lc2  <<<dim3(66, 8),   128>>>(lc2w, lc2b);
    kred    <<<1, 1024>>>(1, 528, 8,  1.0f / (8192.0f * 66.0f), g2, be2);
    k5_lc3  <<<dim3(48, 8),   128>>>(lc3w, lc3b);
    kred    <<<1, 1024>>>(2, 384, 8,  1.0f / (8192.0f * 48.0f), g3, be3);
    k7_out  <<<dim3(12, 128), 256>>>(out);
}